// round 2
// baseline (speedup 1.0000x reference)
#include <cuda_runtime.h>

#define BB    32
#define NP    192
#define CC    128
#define NSS   36
#define MID   64
#define FCH   128
#define EPS   1e-5f
#define NTOT  (BB*NP)      // 6144
#define LL    250
#define KFC   (CC*NSS)     // 4608

// ---------------- scratch (device globals; no runtime allocation) -------------
__device__ float g_cat1[NTOT * 192 * NSS];   // level conv outputs, concatenated
__device__ float g_cat2[NTOT * CC * NSS];    // cat conv output
__device__ float g_roi [BB * NP * FCH];      // fc+LN+ReLU output
__device__ float g_k   [BB * CC * LL];       // keys   (b, f, l)
__device__ float g_v   [BB * LL * CC];       // values (b, l, f)
__device__ float g_fcwT[KFC * FCH];          // fc_w transposed (k, f)

// ---------------- fc_w transpose -------------------------------------------
__global__ void transpose_fcw(const float* __restrict__ w) {
    int idx = blockIdx.x * 256 + threadIdx.x;
    if (idx < FCH * KFC) {
        int f = idx % FCH, k = idx / FCH;
        g_fcwT[idx] = w[f * KFC + k];
    }
}

// ---------------- generic conv9 + folded BN + ReLU --------------------------
// out[n, c0+m, s] = relu( BN( sum_{ci,t} w[m,ci,t] * x[n,ci,s+t-4] ) )
// Block tile: COUT x (NSAMP*36). Thread tile: 8 (M) x 9 (N).
template<int CIN, int COUT, int NSAMP>
__global__ __launch_bounds__(256, 2)
void conv_bn_relu(const float* __restrict__ x, const float* __restrict__ w,
                  const float* __restrict__ bn_g, const float* __restrict__ bn_b,
                  const float* __restrict__ bn_m, const float* __restrict__ bn_v,
                  float* __restrict__ out, int out_cstride, int out_c0) {
    constexpr int TN = NSAMP * 4;      // threads along N (32 or 16)
    constexpr int TM = 256 / TN;       // threads along M (8 or 16)
    static_assert(TM * 8 == COUT, "tiling");

    __shared__ float w_s[COUT * 72];       // [m][ci*9+t] for 8-ci chunk
    __shared__ float x_s[NSAMP * 356];     // [samp][ci][44], samp stride 356 (pad)

    const int tid  = threadIdx.x;
    const int tn   = tid % TN, tm = tid / TN;
    const int samp = tn % NSAMP, sb = tn / NSAMP;   // sb in 0..3, 9 cols each
    const int n0   = blockIdx.x * NSAMP;

    // zero whole x tile once (pads stay zero across chunks)
    for (int i = tid; i < NSAMP * 356; i += 256) x_s[i] = 0.f;

    float acc[8][9];
#pragma unroll
    for (int a = 0; a < 8; a++)
#pragma unroll
        for (int j = 0; j < 9; j++) acc[a][j] = 0.f;

    const int xbase = samp * 356 + sb * 9;

    for (int kc = 0; kc < CIN / 8; kc++) {
        __syncthreads();
        // stage 8-ci weight chunk: contiguous 72 floats per output row
        for (int i = tid; i < COUT * 72; i += 256) {
            int m = i / 72, inner = i % 72;
            w_s[i] = w[m * CIN * 9 + kc * 72 + inner];
        }
        // stage input chunk (data region only; +4 left pad offset)
        for (int i = tid; i < NSAMP * 8 * 36; i += 256) {
            int s = i % 36, ci = (i / 36) % 8, sp = i / 288;
            x_s[sp * 356 + ci * 44 + s + 4] =
                x[((n0 + sp) * CIN + kc * 8 + ci) * 36 + s];
        }
        __syncthreads();

#pragma unroll 1
        for (int ci = 0; ci < 8; ci++) {
            float win[17];                    // sliding window: 1 LDS per new tap
#pragma unroll
            for (int wd = 0; wd < 17; wd++) win[wd] = x_s[xbase + ci * 44 + wd];
#pragma unroll
            for (int t = 0; t < 9; t++) {
                float a[8];
#pragma unroll
                for (int mm = 0; mm < 8; mm++)
                    a[mm] = w_s[(tm * 8 + mm) * 72 + ci * 9 + t];
#pragma unroll
                for (int mm = 0; mm < 8; mm++)
#pragma unroll
                    for (int j = 0; j < 9; j++)
                        acc[mm][j] = fmaf(a[mm], win[t + j], acc[mm][j]);
            }
        }
    }

    // epilogue: folded BN + ReLU
#pragma unroll
    for (int mm = 0; mm < 8; mm++) {
        int m = tm * 8 + mm;
        float sc = bn_g[m] * rsqrtf(bn_v[m] + EPS);
        float bi = bn_b[m] - bn_m[m] * sc;
#pragma unroll
        for (int j = 0; j < 9; j++) {
            int s = sb * 9 + j;
            float vv = fmaf(acc[mm][j], sc, bi);
            out[((n0 + samp) * out_cstride + out_c0 + m) * 36 + s] =
                vv > 0.f ? vv : 0.f;
        }
    }
}

// ---------------- FC (6144x128 <- K=4608) fused with LayerNorm + ReLU --------
__global__ __launch_bounds__(256, 2)
void fc_ln_relu(const float* __restrict__ fc_b, const float* __restrict__ ln_g,
                const float* __restrict__ ln_b) {
    __shared__ float A_s[64 * 33];
    __shared__ float B_s[32 * 128];
    const int tid = threadIdx.x;
    const int tn = tid % 16, tm = tid / 16;   // m = tm*4+mi, f = tn + 16*j
    const int n0 = blockIdx.x * 64;

    float acc[4][8];
#pragma unroll
    for (int a = 0; a < 4; a++)
#pragma unroll
        for (int j = 0; j < 8; j++) acc[a][j] = 0.f;

    for (int k0 = 0; k0 < KFC; k0 += 32) {
        __syncthreads();
        for (int i = tid; i < 64 * 32; i += 256) {
            int kk = i % 32, mr = i / 32;
            A_s[mr * 33 + kk] = g_cat2[(n0 + mr) * KFC + k0 + kk];
        }
        for (int i = tid; i < 32 * 128; i += 256) {
            int f = i % 128, kk = i / 128;
            B_s[kk * 128 + f] = g_fcwT[(k0 + kk) * 128 + f];
        }
        __syncthreads();
#pragma unroll 4
        for (int kk = 0; kk < 32; kk++) {
            float a[4], b[8];
#pragma unroll
            for (int mi = 0; mi < 4; mi++) a[mi] = A_s[(tm * 4 + mi) * 33 + kk];
#pragma unroll
            for (int j = 0; j < 8; j++) b[j] = B_s[kk * 128 + tn + 16 * j];
#pragma unroll
            for (int mi = 0; mi < 4; mi++)
#pragma unroll
                for (int j = 0; j < 8; j++)
                    acc[mi][j] = fmaf(a[mi], b[j], acc[mi][j]);
        }
    }

    // bias + LayerNorm (128 feats live in 16 lanes x 8 regs) + ReLU
#pragma unroll
    for (int mi = 0; mi < 4; mi++) {
        float sum = 0.f;
#pragma unroll
        for (int j = 0; j < 8; j++) {
            acc[mi][j] += fc_b[tn + 16 * j];
            sum += acc[mi][j];
        }
        for (int d = 8; d >= 1; d >>= 1) sum += __shfl_xor_sync(0xffffffffu, sum, d);
        float mean = sum * (1.f / 128.f);
        float sq = 0.f;
#pragma unroll
        for (int j = 0; j < 8; j++) {
            float dd = acc[mi][j] - mean;
            sq += dd * dd;
        }
        for (int d = 8; d >= 1; d >>= 1) sq += __shfl_xor_sync(0xffffffffu, sq, d);
        float rstd = rsqrtf(sq * (1.f / 128.f) + EPS);
        int m = tm * 4 + mi;
#pragma unroll
        for (int j = 0; j < 8; j++) {
            int f = tn + 16 * j;
            float val = (acc[mi][j] - mean) * rstd * ln_g[f] + ln_b[f];
            g_roi[(n0 + m) * 128 + f] = fmaxf(val, 0.f);
        }
    }
}

// ---------------- k/v at the 250 nearest-resize sample points ----------------
// sample (h,w) = (4r, 4c); l = r*25 + c.  k: BN+ReLU(key_w @ fmap), v: val_w@fmap+b
__global__ __launch_bounds__(256)
void kv_kernel(const float* __restrict__ fmap, const float* __restrict__ key_w,
               const float* __restrict__ key_g, const float* __restrict__ key_beta,
               const float* __restrict__ key_m, const float* __restrict__ key_v,
               const float* __restrict__ val_w, const float* __restrict__ val_b) {
    __shared__ float fc_s[25 * 129];
    const int b = blockIdx.x, r = blockIdx.y;
    const int tid = threadIdx.x;
    for (int i = tid; i < 25 * 128; i += 256) {
        int c = i / 25, pos = i % 25;
        fc_s[pos * 129 + c] = fmap[((b * 128 + c) * 40 + 4 * r) * 100 + 4 * pos];
    }
    __syncthreads();
    for (int i = tid; i < 25 * 128; i += 256) {
        int o = i % 128, pos = i / 128;
        const float* kw = key_w + o * 128;
        const float* vw = val_w + o * 128;
        float ka = 0.f, va = 0.f;
#pragma unroll 4
        for (int c = 0; c < 128; c++) {
            float xv = fc_s[pos * 129 + c];
            ka = fmaf(kw[c], xv, ka);
            va = fmaf(vw[c], xv, va);
        }
        float sc = key_g[o] * rsqrtf(key_v[o] + EPS);
        float kb = key_beta[o] - key_m[o] * sc;
        float kk = fmaf(ka, sc, kb);
        int l = r * 25 + pos;
        g_k[(b * 128 + o) * LL + l] = kk > 0.f ? kk : 0.f;
        g_v[(b * LL + l) * 128 + o] = va + val_b[o];
    }
}

// ---------------- attention: block = (b, 32 priors) --------------------------
__global__ __launch_bounds__(256)
void attn_kernel(const float* __restrict__ q_w, const float* __restrict__ q_b,
                 const float* __restrict__ gate_w, const float* __restrict__ gate_b,
                 float* __restrict__ out) {
    __shared__ float q_s[32 * 129];     // reused as v chunk later (needs 32*128)
    __shared__ float p_s[32 * 251];
    const int b = blockIdx.x, p0 = blockIdx.y * 32;
    const int tid = threadIdx.x;

    for (int i = tid; i < 32 * 128; i += 256) {
        int p = i / 128, f = i % 128;
        float qq = fmaf(g_roi[(b * NP + p0 + p) * 128 + f], q_w[p0 + p], q_b[p0 + p]);
        q_s[p * 129 + f] = qq > 0.f ? qq : 0.f;
    }
    __syncthreads();

    const float scale = 0.08838834764831845f;  // 128^-0.5
    for (int idx = tid; idx < 32 * LL; idx += 256) {
        int p = idx % 32, l = idx / 32;        // warp-uniform l -> broadcast k reads
        const float* krow = g_k + b * 128 * LL + l;
        float a = 0.f;
#pragma unroll 4
        for (int f = 0; f < 128; f++)
            a = fmaf(q_s[p * 129 + f], krow[f * LL], a);
        p_s[p * 251 + l] = a * scale;
    }
    __syncthreads();

    // softmax: each warp handles 4 rows
    const int warp = tid / 32, lane = tid % 32;
    for (int rr = 0; rr < 4; rr++) {
        int p = warp * 4 + rr;
        float mx = -1e30f;
        for (int l = lane; l < LL; l += 32) mx = fmaxf(mx, p_s[p * 251 + l]);
        for (int d = 16; d >= 1; d >>= 1) mx = fmaxf(mx, __shfl_xor_sync(~0u, mx, d));
        float sm = 0.f;
        for (int l = lane; l < LL; l += 32) {
            float e = __expf(p_s[p * 251 + l] - mx);
            p_s[p * 251 + l] = e;
            sm += e;
        }
        for (int d = 16; d >= 1; d >>= 1) sm += __shfl_xor_sync(~0u, sm, d);
        float inv = 1.f / sm;
        for (int l = lane; l < LL; l += 32) p_s[p * 251 + l] *= inv;
    }
    __syncthreads();

    // ctx = probs @ v  (v chunks staged in smem, reusing q_s area)
    float* v_s = q_s;
    float acc[16];
#pragma unroll
    for (int it = 0; it < 16; it++) acc[it] = 0.f;
    const int f = tid % 128, pb = tid / 128;   // p = pb + 2*it
    for (int lc = 0; lc < LL; lc += 32) {
        int lim = min(32, LL - lc);
        __syncthreads();
        for (int i = tid; i < lim * 128; i += 256)
            v_s[i] = g_v[(b * LL + lc + i / 128) * 128 + (i % 128)];
        __syncthreads();
#pragma unroll
        for (int it = 0; it < 16; it++) {
            int p = pb + 2 * it;
            float a = acc[it];
            for (int l = 0; l < lim; l++)
                a = fmaf(p_s[p * 251 + lc + l], v_s[l * 128 + f], a);
            acc[it] = a;
        }
    }
#pragma unroll
    for (int it = 0; it < 16; it++) {
        int gp = p0 + pb + 2 * it;
        float ctx = fmaf(acc[it], gate_w[gp], gate_b[gp]);
        out[(b * NP + gp) * 128 + f] = g_roi[(b * NP + gp) * 128 + f] + ctx;
    }
}

// ---------------- host launcher ---------------------------------------------
extern "C" void kernel_launch(void* const* d_in, const int* in_sizes, int n_in,
                              void* d_out, int out_size) {
    (void)in_sizes; (void)n_in; (void)out_size;
    const float* roi0   = (const float*)d_in[0];
    const float* roi1   = (const float*)d_in[1];
    const float* roi2   = (const float*)d_in[2];
    const float* fmap   = (const float*)d_in[3];
    const float* conv_w = (const float*)d_in[4];
    const float* conv_g = (const float*)d_in[5];
    const float* conv_b = (const float*)d_in[6];
    const float* conv_m = (const float*)d_in[7];
    const float* conv_v = (const float*)d_in[8];
    const float* cat_w  = (const float*)d_in[9];
    const float* cat_g  = (const float*)d_in[10];
    const float* cat_b  = (const float*)d_in[11];
    const float* cat_m  = (const float*)d_in[12];
    const float* cat_v  = (const float*)d_in[13];
    const float* fc_w   = (const float*)d_in[14];
    const float* fc_b   = (const float*)d_in[15];
    const float* ln_g   = (const float*)d_in[16];
    const float* ln_b   = (const float*)d_in[17];
    const float* key_w  = (const float*)d_in[18];
    const float* key_g  = (const float*)d_in[19];
    const float* key_bt = (const float*)d_in[20];
    const float* key_m  = (const float*)d_in[21];
    const float* key_v  = (const float*)d_in[22];
    const float* q_w    = (const float*)d_in[23];
    const float* q_b    = (const float*)d_in[24];
    const float* val_w  = (const float*)d_in[25];
    const float* val_b  = (const float*)d_in[26];
    const float* gate_w = (const float*)d_in[27];
    const float* gate_b = (const float*)d_in[28];
    float* out = (float*)d_out;

    float *cat1, *cat2;
    cudaGetSymbolAddress((void**)&cat1, g_cat1);
    cudaGetSymbolAddress((void**)&cat2, g_cat2);

    transpose_fcw<<<(FCH * KFC + 255) / 256, 256>>>(fc_w);

    // three level convs -> g_cat1 channels [lvl*64, lvl*64+64)
    for (int lvl = 0; lvl < 3; lvl++) {
        const float* x = (lvl == 0) ? roi0 : (lvl == 1) ? roi1 : roi2;
        conv_bn_relu<128, 64, 8><<<NTOT / 8, 256>>>(
            x, conv_w + lvl * 64 * 128 * 9,
            conv_g + lvl * 64, conv_b + lvl * 64, conv_m + lvl * 64, conv_v + lvl * 64,
            cat1, 192, lvl * 64);
    }
    // cat conv -> g_cat2
    conv_bn_relu<192, 128, 4><<<NTOT / 4, 256>>>(
        cat1, cat_w, cat_g, cat_b, cat_m, cat_v, cat2, 128, 0);

    fc_ln_relu<<<NTOT / 64, 256>>>(fc_b, ln_g, ln_b);

    kv_kernel<<<dim3(BB, 10), 256>>>(fmap, key_w, key_g, key_bt, key_m, key_v,
                                     val_w, val_b);

    attn_kernel<<<dim3(BB, NP / 32), 256>>>(q_w, q_b, gate_w, gate_b, out);
}